// round 9
// baseline (speedup 1.0000x reference)
#include <cuda_runtime.h>
#include <cuda_bf16.h>
#include <stdint.h>
#include <math.h>

// Problem constants
#define B_      32
#define CIN     512
#define HW      4096          // 64*64
#define VD      16
#define NCHUNK1 16            // pixel chunks per image in k_root (256 px each)
#define NCHUNK3 16            // chunks per image in k_mant (256 px each)

// Scratch (device globals; no allocation allowed)
__device__ float g_feats0[B_ * VD * HW];          // 8 MB, layout [b][k][pixel]
__device__ float g_pool_part[B_ * NCHUNK1 * VD];  // per-chunk pooled partial sums
__device__ float g_M[B_ * VD * VD];               // composed path matrix per batch
__device__ float g_cvec[B_ * VD];                 // composed path bias per batch
__device__ float g_mpart[B_ * NCHUNK3];           // mantissa partial sums
__device__ int   g_ctr;                           // k_mant completion counter

__constant__ int c_off[4] = {0, 2, 5, 9};         // LEVEL_OFFSETS

// ---- f32x2 packed helpers (Blackwell FFMA2, PTX-only) ----------------------
__device__ __forceinline__ unsigned long long pack2(float lo, float hi) {
    unsigned long long r;
    asm("mov.b64 %0, {%1, %2};" : "=l"(r) : "f"(lo), "f"(hi));
    return r;
}
__device__ __forceinline__ void fma2(unsigned long long& d,
                                     unsigned long long a,
                                     unsigned long long b) {
    asm("fma.rn.f32x2 %0, %1, %2, %0;" : "+l"(d) : "l"(a), "l"(b));
}
__device__ __forceinline__ void unpack2(unsigned long long p, float& lo, float& hi) {
    asm("mov.b64 {%0, %1}, %2;" : "=f"(lo), "=f"(hi) : "l"(p));
}

// ---------------------------------------------------------------------------
// Kernel 1: feats0 = root_w @ features + root_b, plus pooled partial sums.
// grid (NCHUNK1, B_) = 512 blocks x 256 threads; ONE pixel per thread, all 16
// outputs as 8 packed k-pairs (acc = 16 regs). Weights transposed in smem
// (32 KB, non-duplicated: ws[c*16+k] so (k0,k1) pairs are LDS.128-adjacent,
// broadcast across the warp). x duplicated per channel with one mov.b64.
// Double-buffered 4-channel groups keep 8 LDG.32 in flight per thread.
// 4 blocks/SM (64-reg budget) -> 32 warps/SM, single wave (512 <= 4*148).
// ---------------------------------------------------------------------------
__global__ __launch_bounds__(256, 4)
void k_root(const float* __restrict__ feat,
            const float* __restrict__ rw,   // (16, 512)
            const float* __restrict__ rb)   // (16,)
{
    __shared__ float ws[CIN * VD];          // 32 KB: ws[c*16+k] = rw[k*512+c]
    __shared__ float wpool[8][VD];          // per-warp pooled partials

    const int t     = threadIdx.x;
    const int chunk = blockIdx.x;
    const int b     = blockIdx.y;
    const int px    = chunk * 256 + t;      // this thread's pixel

    for (int i = t; i < CIN * VD; i += 256) {
        int c = i >> 4, k = i & 15;
        ws[i] = rw[k * CIN + c];
    }

    // 8 packed accumulators: acc[p] = (out_{2p}, out_{2p+1}), seeded with bias
    unsigned long long acc[8];
#pragma unroll
    for (int p = 0; p < 8; p++)
        acc[p] = pack2(__ldg(&rb[2 * p]), __ldg(&rb[2 * p + 1]));
    __syncthreads();

    const float* gb = feat + (size_t)b * CIN * HW + px;

    float xA[4], xB[4];
#define LOADX(X, C0)                                                           \
    {                                                                          \
        X[0] = gb[(size_t)((C0) + 0) * HW];                                    \
        X[1] = gb[(size_t)((C0) + 1) * HW];                                    \
        X[2] = gb[(size_t)((C0) + 2) * HW];                                    \
        X[3] = gb[(size_t)((C0) + 3) * HW];                                    \
    }
#define COMPX(X, C0)                                                           \
    {                                                                          \
        _Pragma("unroll")                                                      \
        for (int j = 0; j < 4; j++) {                                          \
            unsigned long long xd = pack2(X[j], X[j]);                         \
            const ulonglong2* wr = reinterpret_cast<const ulonglong2*>(        \
                ws + ((C0) + j) * VD);                                         \
            ulonglong2 wa = wr[0], wb2 = wr[1];                                \
            fma2(acc[0], wa.x,  xd);                                           \
            fma2(acc[1], wa.y,  xd);                                           \
            fma2(acc[2], wb2.x, xd);                                           \
            fma2(acc[3], wb2.y, xd);                                           \
            ulonglong2 wc = wr[2], wd = wr[3];                                 \
            fma2(acc[4], wc.x,  xd);                                           \
            fma2(acc[5], wc.y,  xd);                                           \
            fma2(acc[6], wd.x,  xd);                                           \
            fma2(acc[7], wd.y,  xd);                                           \
        }                                                                      \
    }

    LOADX(xA, 0);
    for (int c = 0; c < CIN; c += 8) {
        LOADX(xB, c + 4);
        COMPX(xA, c);
        if (c + 8 < CIN) LOADX(xA, c + 8);
        COMPX(xB, c + 4);
    }
#undef LOADX
#undef COMPX

    // Epilogue: unpack, store feats0 (coalesced per k-plane), pool-reduce
    float v[16];
#pragma unroll
    for (int p = 0; p < 8; p++) unpack2(acc[p], v[2 * p], v[2 * p + 1]);

    float* ob = g_feats0 + (size_t)b * VD * HW + px;
#pragma unroll
    for (int k = 0; k < VD; k++) ob[(size_t)k * HW] = v[k];

    // Warp shuffle reduce all 16 values, then block-combine 8 warps
#pragma unroll
    for (int off = 16; off > 0; off >>= 1) {
#pragma unroll
        for (int k = 0; k < VD; k++)
            v[k] += __shfl_xor_sync(0xffffffffu, v[k], off);
    }
    const int wid = t >> 5, lane = t & 31;
    if (lane < VD && wid < 8) wpool[wid][lane] = 0.f;  // (init not needed; overwritten)
    if (lane == 0) {
#pragma unroll
        for (int k = 0; k < VD; k++) wpool[wid][k] = v[k];
    }
    __syncthreads();
    if (t < VD) {
        float s = ((wpool[0][t] + wpool[1][t]) + (wpool[2][t] + wpool[3][t]))
                + ((wpool[4][t] + wpool[5][t]) + (wpool[6][t] + wpool[7][t]));
        g_pool_part[(b * NCHUNK1 + chunk) * VD + t] = s;
    }
}

// ---------------------------------------------------------------------------
// Kernel 2: pooled binomial tree per batch; emits class_logits, selected_class,
// and the composed 16x16 path matrix + bias.  grid: B_, block: 256
// ---------------------------------------------------------------------------
__global__ __launch_bounds__(256)
void k_tree(const float* __restrict__ lw,   // (14,16,16)
            const float* __restrict__ lb,   // (14,16)
            float* __restrict__ out)
{
    const int b   = blockIdx.x;
    const int tid = threadIdx.x;

    __shared__ float P[5][VD], Pn[5][VD];
    __shared__ float norms[5];
    __shared__ int   choice[5][5];
    __shared__ int   path[5];
    __shared__ float M[VD * VD], cv[VD];

    if (tid < VD) {
        float s = 0.f;
#pragma unroll
        for (int c = 0; c < NCHUNK1; c++)
            s += g_pool_part[(b * NCHUNK1 + c) * VD + tid];
        P[0][tid] = s * (1.0f / (float)HW);
    }
    __syncthreads();

    int ncur = 1;
    for (int level = 1; level <= 4; level++) {
        const int off = c_off[level - 1];
        const int nn  = level + 1;
        if (tid < ncur) {
            float s = 0.f;
#pragma unroll
            for (int k = 0; k < VD; k++) s += P[tid][k] * P[tid][k];
            norms[tid] = sqrtf(s);
        }
        __syncthreads();
        if (tid < nn) {
            int pl = tid - 1; if (pl < 0) pl = 0;
            int pr = tid;     if (pr > level - 1) pr = level - 1;
            int ch = pl;
            if (pl != pr && norms[pr] > norms[pl]) ch = pr;
            choice[level][tid] = ch;
        }
        __syncthreads();
        if (tid < nn * VD) {
            int node = tid >> 4, i = tid & 15;
            const float* W = lw + (size_t)(off + node) * VD * VD + i * VD;
            const float* par = P[choice[level][node]];
            float s = lb[(off + node) * VD + i];
#pragma unroll
            for (int k = 0; k < VD; k++) s = fmaf(W[k], par[k], s);
            Pn[node][i] = s;
        }
        __syncthreads();
        if (tid < nn * VD) P[tid >> 4][tid & 15] = Pn[tid >> 4][tid & 15];
        __syncthreads();
        ncur = nn;
    }

    if (tid < 5) {
        float s = 0.f;
#pragma unroll
        for (int k = 0; k < VD; k++) s += P[tid][k] * P[tid][k];
        norms[tid] = sqrtf(s);
        out[b * 5 + tid] = norms[tid];          // class_logits
    }
    __syncthreads();
    if (tid == 0) {
        int best = 0; float bv = norms[0];
        for (int j = 1; j < 5; j++)
            if (norms[j] > bv) { bv = norms[j]; best = j; }
        out[192 + b] = (float)best;             // selected_class
        path[4] = best;
        path[3] = choice[4][path[4]];
        path[2] = choice[3][path[3]];
        path[1] = choice[2][path[2]];
    }
    __syncthreads();

    const int i = tid >> 4, j = tid & 15;
    {
        int idx = c_off[0] + path[1];
        M[tid] = lw[(size_t)idx * 256 + i * 16 + j];
        if (j == 0) cv[i] = lb[idx * 16 + i];
    }
    __syncthreads();
    for (int l = 2; l <= 4; l++) {
        int idx = c_off[l - 1] + path[l];
        const float* W = lw + (size_t)idx * 256;
        float s = 0.f;
#pragma unroll
        for (int k = 0; k < 16; k++) s = fmaf(W[i * 16 + k], M[k * 16 + j], s);
        float sc = 0.f;
        if (j == 0) {
            sc = lb[idx * 16 + i];
#pragma unroll
            for (int k = 0; k < 16; k++) sc = fmaf(W[i * 16 + k], cv[k], sc);
        }
        __syncthreads();
        M[tid] = s;
        if (j == 0) cv[i] = sc;
        __syncthreads();
    }
    g_M[b * 256 + tid] = M[tid];
    if (j == 0) g_cvec[b * VD + i] = cv[i];
}

// ---------------------------------------------------------------------------
// Kernel 3: per-pixel selected feature -> normalize -> MLP(64) -> scalar sum,
// with fused finalization in the last block (threadfence + counter).
// grid: (NCHUNK3, B_), block: 256 (1 pixel/thread)
// ---------------------------------------------------------------------------
__global__ __launch_bounds__(256)
void k_mant(const float* __restrict__ m1w,  // (64,16)
            const float* __restrict__ m1b,  // (64,)
            const float* __restrict__ m2w,  // (1,64)
            const float* __restrict__ m2b,  // (1,)
            float* __restrict__ out)
{
    __shared__ float Ms[256], cs[VD], w1[64 * VD], b1[64], w2[64];
    __shared__ int is_last;
    const int tid   = threadIdx.x;
    const int chunk = blockIdx.x;
    const int b     = blockIdx.y;

    Ms[tid] = g_M[b * 256 + tid];
    if (tid < VD) cs[tid] = g_cvec[b * VD + tid];
    for (int idx = tid; idx < 64 * VD; idx += 256) w1[idx] = m1w[idx];
    if (tid < 64) { b1[tid] = m1b[tid]; w2[tid] = m2w[tid]; }
    __syncthreads();

    const int p = chunk * 256 + tid;
    const float* f0 = g_feats0 + (size_t)b * VD * HW + p;

    float x[VD];
#pragma unroll
    for (int k = 0; k < VD; k++) x[k] = f0[(size_t)k * HW];

    float v[VD];
#pragma unroll
    for (int i = 0; i < VD; i++) {
        float s = cs[i];
#pragma unroll
        for (int k = 0; k < VD; k++) s = fmaf(Ms[i * VD + k], x[k], s);
        v[i] = s;
    }
    float nrm = 0.f;
#pragma unroll
    for (int i = 0; i < VD; i++) nrm = fmaf(v[i], v[i], nrm);
    float inv = 1.0f / (sqrtf(nrm) + 1e-8f);
    float u[VD];
#pragma unroll
    for (int k = 0; k < VD; k++) u[k] = v[k] * inv;

    float s2 = 0.f;
#pragma unroll 4
    for (int jj = 0; jj < 64; jj++) {
        float t = b1[jj];
#pragma unroll
        for (int k = 0; k < VD; k++) t = fmaf(w1[jj * VD + k], u[k], t);
        t = fmaxf(t, 0.f);
        s2 = fmaf(w2[jj], t, s2);
    }

#pragma unroll
    for (int off = 16; off > 0; off >>= 1)
        s2 += __shfl_xor_sync(0xffffffffu, s2, off);
    __shared__ float rs[8];
    int wid = tid >> 5, lane = tid & 31;
    if (lane == 0) rs[wid] = s2;
    __syncthreads();
    if (tid == 0) {
        float t = ((rs[0] + rs[1]) + (rs[2] + rs[3])) +
                  ((rs[4] + rs[5]) + (rs[6] + rs[7]));
        g_mpart[b * NCHUNK3 + chunk] = t;
    }

    // Last-block finalization (deterministic fixed-order sums)
    if (tid == 0) {
        __threadfence();
        int v2 = atomicAdd(&g_ctr, 1);
        is_last = (v2 == (int)(gridDim.x * gridDim.y) - 1);
    }
    __syncthreads();
    if (is_last) {
        if (tid < B_) {
            float s = 0.f;
#pragma unroll
            for (int c = 0; c < NCHUNK3; c++) s += g_mpart[tid * NCHUNK3 + c];
            float mr = s * (1.0f / (float)HW) + m2b[0];
            float sig = 1.0f / (1.0f + expf(-mr));
            out[160 + tid] = sig * 0.75f + 0.75f;
        }
        if (tid == 0) g_ctr = 0;   // reset for next graph replay
    }
}

// ---------------------------------------------------------------------------
extern "C" void kernel_launch(void* const* d_in, const int* in_sizes, int n_in,
                              void* d_out, int out_size)
{
    const float* features = (const float*)d_in[0];
    const float* root_w   = (const float*)d_in[1];
    const float* root_b   = (const float*)d_in[2];
    const float* level_w  = (const float*)d_in[3];
    const float* level_b  = (const float*)d_in[4];
    const float* m1_w     = (const float*)d_in[5];
    const float* m1_b     = (const float*)d_in[6];
    const float* m2_w     = (const float*)d_in[7];
    const float* m2_b     = (const float*)d_in[8];
    float* out = (float*)d_out;

    dim3 g1(NCHUNK1, B_);
    k_root<<<g1, 256>>>(features, root_w, root_b);

    k_tree<<<B_, 256>>>(level_w, level_b, out);

    dim3 g3(NCHUNK3, B_);
    k_mant<<<g3, 256>>>(m1_w, m1_b, m2_w, m2_b, out);
}